// round 5
// baseline (speedup 1.0000x reference)
#include <cuda_runtime.h>
#include <cuda_bf16.h>
#include <stdint.h>

#define MAX_N 100000
#define MAX_E 1000000
#define D 64

// Scratch (device globals; no allocation allowed)
__device__ float g_deg[MAX_N];
__device__ float g_dis[MAX_N];
__device__ __align__(16) float g_y[(size_t)MAX_N * D];   // y = x @ W^T (25.6 MB)
__device__ int g_is64;   // 1 if edge_index is int64, 0 if int32

// ---------------------------------------------------------------------------
// 0) detect edge_index dtype. Indices < N < 2^17. If buffer is really int32,
//    an int64 read combines two indices -> value >= 2^32 almost surely.
__global__ void k_detect(const void* __restrict__ ei, int E, int n) {
    if (threadIdx.x == 0 && blockIdx.x == 0) g_is64 = 1;
    __syncthreads();
    const long long* p = (const long long*)ei;
    int scan = 2 * E < 2048 ? 2 * E : 2048;
    for (int i = threadIdx.x; i < scan; i += blockDim.x) {
        long long v = p[i];
        if (v < 0 || v >= (long long)n) { g_is64 = 0; break; }
    }
}

__device__ __forceinline__ int edge_idx(const void* ei, size_t pos, int is64) {
    return is64 ? (int)((const long long*)ei)[pos] : ((const int*)ei)[pos];
}

// 1) deg init to 1.0 (self-loop contribution)
__global__ void k_deg_init(int n) {
    int i = blockIdx.x * blockDim.x + threadIdx.x;
    if (i < n) g_deg[i] = 1.0f;
}

// 2) deg accumulate over edges: deg[row] += ew
__global__ void k_deg_acc(const void* __restrict__ ei,
                          const float* __restrict__ ew, int E, int n) {
    int e = blockIdx.x * blockDim.x + threadIdx.x;
    if (e < E) {
        int is64 = g_is64;
        int r = edge_idx(ei, e, is64);
        if ((unsigned)r < (unsigned)n) atomicAdd(&g_deg[r], ew[e]);
    }
}

// 3) dis = rsqrt(deg)   (deg >= 1 via self-loop)
__global__ void k_dis(int n) {
    int i = blockIdx.x * blockDim.x + threadIdx.x;
    if (i < n) g_dis[i] = rsqrtf(g_deg[i]);
}

// 4) y = x @ W^T.  W is [D_OUT, D_IN] row-major.
__global__ void k_gemm(const float* __restrict__ x,
                       const float* __restrict__ W, int n) {
    __shared__ float sWt[D * D];   // sWt[k*64+j] = W[j*64+k]
    __shared__ float sx[4][D];
    for (int i = threadIdx.x; i < D * D; i += 256) {
        int j = i >> 6, k = i & 63;
        sWt[k * D + j] = W[i];
    }
    __syncthreads();
    int j  = threadIdx.x & 63;
    int rl = threadIdx.x >> 6;     // 0..3
    int base = blockIdx.x * 32;
    for (int rr = 0; rr < 32; rr += 4) {
        int r = base + rr + rl;
        __syncthreads();
        if (r < n) sx[rl][j] = x[(size_t)r * D + j];
        __syncthreads();
        if (r < n) {
            float acc = 0.0f;
            #pragma unroll
            for (int k = 0; k < D; k++)
                acc = fmaf(sx[rl][k], sWt[k * D + j], acc);
            g_y[(size_t)r * D + j] = acc;
        }
    }
}

// 5) out init: bias + self-loop message  y[i]*dis[i]^2
__global__ void k_out_init(const float* __restrict__ bias,
                           float* __restrict__ out, int n) {
    int t = blockIdx.x * blockDim.x + threadIdx.x;
    if (t < n * D) {
        int node = t >> 6;
        int d    = t & 63;
        float s  = g_dis[node];
        out[t] = bias[d] + g_y[t] * s * s;
    }
}

// 6) edge scatter: 16 threads/edge, one float4 chunk each.
//    norm = dis[row]*ew*dis[col]; out[row] += y[col]*norm  (vector RED)
__global__ void k_scatter(const void* __restrict__ ei,
                          const float* __restrict__ ew,
                          float* __restrict__ out, int E, int n) {
    long long t = (long long)blockIdx.x * blockDim.x + threadIdx.x;
    int e = (int)(t >> 4);
    if (e >= E) return;
    int is64 = g_is64;
    int c  = ((int)t & 15) << 2;                 // chunk offset in [0,64)
    int r  = edge_idx(ei, e, is64);              // scatter target
    int cl = edge_idx(ei, (size_t)E + e, is64);  // gather source
    if ((unsigned)r >= (unsigned)n || (unsigned)cl >= (unsigned)n) return;
    float norm = g_dis[r] * ew[e] * g_dis[cl];
    const float4 v = *reinterpret_cast<const float4*>(&g_y[(size_t)cl * D + c]);
    float* p = &out[(size_t)r * D + c];
    asm volatile("red.global.add.v4.f32 [%0], {%1,%2,%3,%4};"
                 :: "l"(p),
                    "f"(v.x * norm), "f"(v.y * norm),
                    "f"(v.z * norm), "f"(v.w * norm)
                 : "memory");
}

// ---------------------------------------------------------------------------
extern "C" void kernel_launch(void* const* d_in, const int* in_sizes, int n_in,
                              void* d_out, int out_size) {
    const float* x    = (const float*)d_in[0];   // [N,64] f32
    const void*  ei   = d_in[1];                 // [2,E] i64 or i32
    const float* ew   = (const float*)d_in[2];   // [E]   f32
    const float* W    = (const float*)d_in[3];   // [64,64] f32
    const float* bias = (const float*)d_in[4];   // [64]  f32
    float*       out  = (float*)d_out;           // [N,64] f32

    int N = in_sizes[0] / D;
    int E = in_sizes[1] / 2;
    if (N > MAX_N) N = MAX_N;
    if (E > MAX_E) E = MAX_E;

    const int B = 256;
    k_detect  <<<1, 256>>>(ei, E, N);
    k_deg_init<<<(N + B - 1) / B, B>>>(N);
    k_deg_acc <<<(E + B - 1) / B, B>>>(ei, ew, E, N);
    k_dis     <<<(N + B - 1) / B, B>>>(N);
    k_gemm    <<<(N + 31) / 32, 256>>>(x, W, N);
    k_out_init<<<((long long)N * D + B - 1) / B, B>>>(bias, out, N);
    long long scat_threads = (long long)E * 16;
    k_scatter <<<(unsigned)((scat_threads + B - 1) / B), B>>>(ei, ew, out, E, N);
}

// round 6
// speedup vs baseline: 1.1219x; 1.1219x over previous
#include <cuda_runtime.h>
#include <cuda_bf16.h>
#include <stdint.h>

#define MAX_N 100000
#define MAX_E 1000000
#define D 64
#define NB_MAX 1024          // MAX_N/256 = 391 <= 1024

// Scratch (device globals; no allocation allowed)
__device__ float g_deg[MAX_N];
__device__ float g_dis[MAX_N];
__device__ int   g_cnt[MAX_N];
__device__ int   g_base[MAX_N];
__device__ int   g_pos[MAX_N];
__device__ int   g_bsum[NB_MAX];
__device__ __align__(16) float  g_y[(size_t)MAX_N * D];     // y = x @ W^T
__device__ __align__(16) float2 g_epack[MAX_E];             // (col, norm) CSR-ordered
__device__ int g_is64;

// ---------------------------------------------------------------------------
// 0) detect edge_index dtype (int64 vs int32); indices < N << 2^31.
__global__ void k_detect(const void* __restrict__ ei, int E, int n) {
    if (threadIdx.x == 0) g_is64 = 1;
    __syncthreads();
    const long long* p = (const long long*)ei;
    int scan = 2 * E < 2048 ? 2 * E : 2048;
    for (int i = threadIdx.x; i < scan; i += blockDim.x) {
        long long v = p[i];
        if (v < 0 || v >= (long long)n) { g_is64 = 0; break; }
    }
}

__device__ __forceinline__ int edge_idx(const void* ei, size_t pos, int is64) {
    return is64 ? (int)((const long long*)ei)[pos] : ((const int*)ei)[pos];
}

// 1) init: deg = 1 (self-loop), cnt = 0
__global__ void k_init(int n) {
    int i = blockIdx.x * blockDim.x + threadIdx.x;
    if (i < n) { g_deg[i] = 1.0f; g_cnt[i] = 0; }
}

// 2) per-edge: deg[row] += ew, cnt[row] += 1
__global__ void k_acc(const void* __restrict__ ei,
                      const float* __restrict__ ew, int E, int n) {
    int e = blockIdx.x * blockDim.x + threadIdx.x;
    if (e >= E) return;
    int is64 = g_is64;
    int r = edge_idx(ei, e, is64);
    if ((unsigned)r < (unsigned)n) {
        atomicAdd(&g_deg[r], ew[e]);
        atomicAdd(&g_cnt[r], 1);
    }
}

// 3) dis = rsqrt(deg)  (deg >= 1 via self-loop)
__global__ void k_dis(int n) {
    int i = blockIdx.x * blockDim.x + threadIdx.x;
    if (i < n) g_dis[i] = rsqrtf(g_deg[i]);
}

// 4a) per-256-node block sums of cnt
__global__ void k_scan1(int n) {
    __shared__ int sm[256];
    int i = blockIdx.x * 256 + threadIdx.x;
    sm[threadIdx.x] = (i < n) ? g_cnt[i] : 0;
    __syncthreads();
    for (int s = 128; s > 0; s >>= 1) {
        if (threadIdx.x < s) sm[threadIdx.x] += sm[threadIdx.x + s];
        __syncthreads();
    }
    if (threadIdx.x == 0) g_bsum[blockIdx.x] = sm[0];
}

// 4b) exclusive scan of block sums (single block, nb <= 1024)
__global__ void k_scan2(int nb) {
    __shared__ int sm[NB_MAX];
    int t = threadIdx.x;
    int orig = (t < nb) ? g_bsum[t] : 0;
    sm[t] = orig;
    __syncthreads();
    for (int off = 1; off < NB_MAX; off <<= 1) {
        int v = (t >= off) ? sm[t - off] : 0;
        __syncthreads();
        sm[t] += v;
        __syncthreads();
    }
    if (t < nb) g_bsum[t] = sm[t] - orig;
}

// 4c) per-node exclusive base = blockbase + within-block exclusive scan
__global__ void k_scan3(int n) {
    __shared__ int sm[256];
    int i = blockIdx.x * 256 + threadIdx.x;
    int c = (i < n) ? g_cnt[i] : 0;
    sm[threadIdx.x] = c;
    __syncthreads();
    for (int off = 1; off < 256; off <<= 1) {
        int v = (threadIdx.x >= off) ? sm[threadIdx.x - off] : 0;
        __syncthreads();
        sm[threadIdx.x] += v;
        __syncthreads();
    }
    if (i < n) {
        int b = g_bsum[blockIdx.x] + sm[threadIdx.x] - c;
        g_base[i] = b;
        g_pos[i]  = b;
    }
}

// 5) y = x @ W^T.  W is [D_OUT, D_IN] row-major.
__global__ void k_gemm(const float* __restrict__ x,
                       const float* __restrict__ W, int n) {
    __shared__ float sWt[D * D];   // sWt[k*64+j] = W[j*64+k]
    __shared__ float sx[4][D];
    for (int i = threadIdx.x; i < D * D; i += 256) {
        int j = i >> 6, k = i & 63;
        sWt[k * D + j] = W[i];
    }
    __syncthreads();
    int j  = threadIdx.x & 63;
    int rl = threadIdx.x >> 6;
    int base = blockIdx.x * 32;
    for (int rr = 0; rr < 32; rr += 4) {
        int r = base + rr + rl;
        __syncthreads();
        if (r < n) sx[rl][j] = x[(size_t)r * D + j];
        __syncthreads();
        if (r < n) {
            float acc = 0.0f;
            #pragma unroll
            for (int k = 0; k < D; k++)
                acc = fmaf(sx[rl][k], sWt[k * D + j], acc);
            g_y[(size_t)r * D + j] = acc;
        }
    }
}

// 6) reorder edges into CSR: g_epack[pos[row]++] = (col, norm)
__global__ void k_reorder(const void* __restrict__ ei,
                          const float* __restrict__ ew, int E, int n) {
    int e = blockIdx.x * blockDim.x + threadIdx.x;
    if (e >= E) return;
    int is64 = g_is64;
    int r  = edge_idx(ei, e, is64);
    int cl = edge_idx(ei, (size_t)E + e, is64);
    if ((unsigned)r >= (unsigned)n || (unsigned)cl >= (unsigned)n) return;
    float nm = g_dis[r] * ew[e] * g_dis[cl];
    int p = atomicAdd(&g_pos[r], 1);
    g_epack[p] = make_float2(__int_as_float(cl), nm);
}

// 7) gather: one warp per node; lane owns 2 output floats.
//    acc = bias + self-loop + sum_e y[col_e]*norm_e ; no atomics.
__global__ void k_gather(const float* __restrict__ bias,
                         float* __restrict__ out, int n) {
    int warp = (blockIdx.x * blockDim.x + threadIdx.x) >> 5;
    int lane = threadIdx.x & 31;
    if (warp >= n) return;
    int node = warp;
    int j = lane << 1;
    float s = g_dis[node];
    float2 yv = *(const float2*)&g_y[(size_t)node * D + j];
    float a0 = bias[j]     + yv.x * s * s;
    float a1 = bias[j + 1] + yv.y * s * s;
    int beg = g_base[node];
    int end = beg + g_cnt[node];
    for (int p = beg; p < end; p++) {
        float2 pk = g_epack[p];                 // uniform per warp (broadcast)
        int   cl = __float_as_int(pk.x);
        float nm = pk.y;
        const float2 v = *(const float2*)&g_y[(size_t)cl * D + j];
        a0 = fmaf(v.x, nm, a0);
        a1 = fmaf(v.y, nm, a1);
    }
    *(float2*)&out[(size_t)node * D + j] = make_float2(a0, a1);
}

// ---------------------------------------------------------------------------
extern "C" void kernel_launch(void* const* d_in, const int* in_sizes, int n_in,
                              void* d_out, int out_size) {
    const float* x    = (const float*)d_in[0];   // [N,64] f32
    const void*  ei   = d_in[1];                 // [2,E] i64 or i32
    const float* ew   = (const float*)d_in[2];   // [E]   f32
    const float* W    = (const float*)d_in[3];   // [64,64] f32
    const float* bias = (const float*)d_in[4];   // [64]  f32
    float*       out  = (float*)d_out;           // [N,64] f32

    int N = in_sizes[0] / D;
    int E = in_sizes[1] / 2;
    if (N > MAX_N) N = MAX_N;
    if (E > MAX_E) E = MAX_E;
    int nb = (N + 255) / 256;

    const int B = 256;
    k_detect <<<1, 256>>>(ei, E, N);
    k_init   <<<nb, B>>>(N);
    k_acc    <<<(E + B - 1) / B, B>>>(ei, ew, E, N);
    k_dis    <<<nb, B>>>(N);
    k_scan1  <<<nb, B>>>(N);
    k_scan2  <<<1, NB_MAX>>>(nb);
    k_scan3  <<<nb, B>>>(N);
    k_gemm   <<<(N + 31) / 32, 256>>>(x, W, N);
    k_reorder<<<(E + B - 1) / B, B>>>(ei, ew, E, N);
    long long gth = (long long)N * 32;
    k_gather <<<(unsigned)((gth + B - 1) / B), B>>>(bias, out, N);
}